// round 3
// baseline (speedup 1.0000x reference)
#include <cuda_runtime.h>
#include <cuda_bf16.h>
#include <cstdint>

#define N_ENT_MAX  50000
#define N_EDGE_MAX 500000
#define HDIM       128

// ---------------- scratch (device globals; no allocations allowed) ----------
__device__ int g_cnt[N_ENT_MAX + 1];
__device__ int g_row_ptr[N_ENT_MAX + 1];
__device__ int g_cursor[N_ENT_MAX];
__device__ int g_src_s[N_EDGE_MAX];   // src sorted by dst
__device__ int g_rel_s[N_EDGE_MAX];   // rel_id sorted by dst
// neigh results as bf16 hi/lo planes: [layer e/n/c][hi=0,lo=1][node*128+col]
__device__ __nv_bfloat16 g_nb[3][2][N_ENT_MAX * HDIM];
// W transposed to [n][k] layout, bf16 hi/lo
__device__ __nv_bfloat16 g_wb[3][2][HDIM * HDIM];

// ---------------- helpers ----------------------------------------------------
__device__ __forceinline__ float tanh_fast(float x) {
    float e = __expf(2.0f * x);
    return 1.0f - __fdividef(2.0f, e + 1.0f);
}
__device__ __forceinline__ uint32_t smem_u32(const void* p) {
    uint32_t a;
    asm("{ .reg .u64 t; cvta.to.shared.u64 t, %1; cvt.u32.u64 %0, t; }"
        : "=r"(a) : "l"(p));
    return a;
}
__device__ __forceinline__ void ldsm4(uint32_t* r, uint32_t addr) {
    asm volatile("ldmatrix.sync.aligned.m8n8.x4.shared.b16 {%0,%1,%2,%3}, [%4];"
                 : "=r"(r[0]), "=r"(r[1]), "=r"(r[2]), "=r"(r[3]) : "r"(addr));
}
__device__ __forceinline__ void mma16816(float* d, const uint32_t* a,
                                         const uint32_t* b) {
    asm volatile(
        "mma.sync.aligned.m16n8k16.row.col.f32.bf16.bf16.f32 "
        "{%0,%1,%2,%3}, {%4,%5,%6,%7}, {%8,%9}, {%0,%1,%2,%3};"
        : "+f"(d[0]), "+f"(d[1]), "+f"(d[2]), "+f"(d[3])
        : "r"(a[0]), "r"(a[1]), "r"(a[2]), "r"(a[3]), "r"(b[0]), "r"(b[1]));
}
// rows are 256B (128 bf16); 16B chunks XOR-swizzled by row&7 -> LDSM conflict-free
__device__ __forceinline__ uint32_t sw_addr(uint32_t base, int row, int kbyte) {
    return base + row * 256 + ((((kbyte >> 4) ^ (row & 7)) << 4) | (kbyte & 15));
}

// ---------------- CSR build --------------------------------------------------
__global__ void k_zero_cnt(int n) {
    int i = blockIdx.x * blockDim.x + threadIdx.x;
    if (i <= n) g_cnt[i] = 0;
}
__global__ void k_hist(const int* __restrict__ dst, int e) {
    int i = blockIdx.x * blockDim.x + threadIdx.x;
    if (i < e) atomicAdd(&g_cnt[dst[i]], 1);
}
__global__ void k_scan(int n) {
    __shared__ int sums[1024];
    int t = threadIdx.x;
    int C = (n + 1023) >> 10;
    int beg = t * C, end = min(beg + C, n);
    int s = 0;
    for (int i = beg; i < end; i++) s += g_cnt[i];
    sums[t] = s;
    __syncthreads();
    for (int off = 1; off < 1024; off <<= 1) {
        int v = 0;
        if (t >= off) v = sums[t - off];
        __syncthreads();
        if (t >= off) sums[t] += v;
        __syncthreads();
    }
    int run = (t == 0) ? 0 : sums[t - 1];
    for (int i = beg; i < end; i++) {
        int c = g_cnt[i];
        g_row_ptr[i] = run;
        g_cursor[i] = run;
        run += c;
    }
    if (t == 1023) g_row_ptr[n] = sums[1023];
}
__global__ void k_fill(const int* __restrict__ dst, const int* __restrict__ src,
                       const int* __restrict__ relid, int e) {
    int i = blockIdx.x * blockDim.x + threadIdx.x;
    if (i < e) {
        int pos = atomicAdd(&g_cursor[dst[i]], 1);
        g_src_s[pos] = src[i];
        g_rel_s[pos] = relid[i];
    }
}

// ---------------- W -> bf16 hi/lo transposed [n][k] --------------------------
__global__ void k_wconv(const float* __restrict__ We, const float* __restrict__ Wn,
                        const float* __restrict__ Wc) {
    int i = blockIdx.x * blockDim.x + threadIdx.x;
    if (i >= 3 * HDIM * HDIM) return;
    int ph = i / (HDIM * HDIM);
    int rem = i - ph * HDIM * HDIM;
    int nn = rem >> 7, kk = rem & 127;
    const float* W = (ph == 0) ? We : (ph == 1) ? Wn : Wc;
    float w = W[kk * HDIM + nn];  // transpose: [n][k]
    __nv_bfloat16 hi = __float2bfloat16(w);
    __nv_bfloat16 lo = __float2bfloat16(w - __bfloat162float(hi));
    g_wb[ph][0][nn * HDIM + kk] = hi;
    g_wb[ph][1][nn * HDIM + kk] = lo;
}

// ---------------- node kernel: one warp per dst node -------------------------
// |logits| <= ~0.5 here (rows near unit norm), so the softmax max-subtraction
// is skipped: exp cannot overflow; result identical.
__global__ __launch_bounds__(256) void k_node(
    const float* __restrict__ ent, const float* __restrict__ rel, int n)
{
    int gw = (blockIdx.x * blockDim.x + threadIdx.x) >> 5;
    int lane = threadIdx.x & 31;
    if (gw >= n) return;

    const float4* ent4 = (const float4*)ent;
    const float4* rel4 = (const float4*)rel;

    int beg = g_row_ptr[gw];
    int end = g_row_ptr[gw + 1];

    float s_e = 0.f, s_n = 0.f, s_c = 0.f;
    float4 acc_e = make_float4(0, 0, 0, 0);
    float4 acc_n = make_float4(0, 0, 0, 0);
    float4 acc_c = make_float4(0, 0, 0, 0);

    if (beg < end) {
        float4 v = ent4[gw * 32 + lane];
        int s0 = g_src_s[beg], r0 = g_rel_s[beg];
        float4 u = ent4[s0 * 32 + lane];
        float4 r = rel4[r0 * 32 + lane];
        for (int i = beg; i < end; i++) {
            float4 uc = u, rc = r;
            int inx = min(i + 1, end - 1);
            int s1 = g_src_s[inx], r1 = g_rel_s[inx];
            u = ent4[s1 * 32 + lane];
            r = rel4[r1 * 32 + lane];

            float duv = uc.x * v.x + uc.y * v.y + uc.z * v.z + uc.w * v.w;
            float drv = rc.x * v.x + rc.y * v.y + rc.z * v.z + rc.w * v.w;
            #pragma unroll
            for (int o = 16; o; o >>= 1) {
                duv += __shfl_xor_sync(0xFFFFFFFFu, duv, o);
                drv += __shfl_xor_sync(0xFFFFFFFFu, drv, o);
            }
            float pe = __expf(drv);
            float pn = __expf(duv);
            float pc = pe * pn;

            s_e += pe;
            acc_e.x += pe * rc.x; acc_e.y += pe * rc.y;
            acc_e.z += pe * rc.z; acc_e.w += pe * rc.w;
            s_n += pn;
            acc_n.x += pn * uc.x; acc_n.y += pn * uc.y;
            acc_n.z += pn * uc.z; acc_n.w += pn * uc.w;
            s_c += pc;
            acc_c.x += pc * (uc.x + rc.x); acc_c.y += pc * (uc.y + rc.y);
            acc_c.z += pc * (uc.z + rc.z); acc_c.w += pc * (uc.w + rc.w);
        }
    }

    float ie = (s_e > 0.f) ? __fdividef(1.f, s_e) : 0.f;
    float in_ = (s_n > 0.f) ? __fdividef(1.f, s_n) : 0.f;
    float ic = (s_c > 0.f) ? __fdividef(1.f, s_c) : 0.f;

    float vals[3][4] = {
        {acc_e.x * ie, acc_e.y * ie, acc_e.z * ie, acc_e.w * ie},
        {acc_n.x * in_, acc_n.y * in_, acc_n.z * in_, acc_n.w * in_},
        {acc_c.x * ic, acc_c.y * ic, acc_c.z * ic, acc_c.w * ic}};
    #pragma unroll
    for (int L = 0; L < 3; L++) {
        uint32_t hp[2], lp[2];
        #pragma unroll
        for (int p = 0; p < 2; p++) {
            float a = vals[L][2 * p], b = vals[L][2 * p + 1];
            __nv_bfloat16 ha = __float2bfloat16(a);
            __nv_bfloat16 hb = __float2bfloat16(b);
            __nv_bfloat16 la = __float2bfloat16(a - __bfloat162float(ha));
            __nv_bfloat16 lb = __float2bfloat16(b - __bfloat162float(hb));
            hp[p] = (uint32_t)__bfloat16_as_ushort(ha) |
                    ((uint32_t)__bfloat16_as_ushort(hb) << 16);
            lp[p] = (uint32_t)__bfloat16_as_ushort(la) |
                    ((uint32_t)__bfloat16_as_ushort(lb) << 16);
        }
        *(uint2*)((char*)g_nb[L][0] + (size_t)gw * 256 + lane * 8) = make_uint2(hp[0], hp[1]);
        *(uint2*)((char*)g_nb[L][1] + (size_t)gw * 256 + lane * 8) = make_uint2(lp[0], lp[1]);
    }
}

// ---------------- HMMA GEMM epilogue -----------------------------------------
// out = ent + sum_ph tanh(neigh_ph @ W_ph); bf16 hi/lo split (AhWh+AlWh+AhWl).
// Block 256 thr = 8 warps; M-tile 64, N=128, K=128.
// warp w: rows mt=w&3 (16 rows), cols nh=w>>2 (64 cols = 8 n-tiles of 8).
#define SM_AH 0
#define SM_AL 16384
#define SM_WH 32768
#define SM_WL 65536
#define SM_TOT 98304

__global__ __launch_bounds__(256, 1) void k_gemm(
    const float* __restrict__ ent, float* __restrict__ out, int n)
{
    extern __shared__ char smem[];
    uint32_t sb = smem_u32(smem);
    int tid = threadIdx.x;
    int w = tid >> 5, lane = tid & 31;
    int mt = w & 3, nh = w >> 2;
    int row_base = blockIdx.x * 64;

    int lane8 = lane & 7, lT = lane >> 3;
    // A ldmatrix lane mapping (tiles: m0k0, m8k0, m0k8, m8k8)
    int rowA = mt * 16 + ((lT & 1) << 3) + lane8;
    int kbA = (lT >> 1) << 4;
    // B ldmatrix lane mapping (tiles: n0k0, n0k8, n8k0, n8k8)
    int rowB0 = nh * 64 + ((lT >> 1) << 3) + lane8;
    int kbB = (lT & 1) << 4;

    // output thread mapping
    int orow = row_base + mt * 16 + (lane >> 2);
    int ocol0 = nh * 64 + (lane & 3) * 2;

    float out_acc[8][4];
    #pragma unroll
    for (int nt = 0; nt < 8; nt++) {
        int col = ocol0 + nt * 8;
        float2 e0 = make_float2(0.f, 0.f), e1 = make_float2(0.f, 0.f);
        if (orow < n)     e0 = *(const float2*)(ent + (size_t)orow * HDIM + col);
        if (orow + 8 < n) e1 = *(const float2*)(ent + (size_t)(orow + 8) * HDIM + col);
        out_acc[nt][0] = e0.x; out_acc[nt][1] = e0.y;
        out_acc[nt][2] = e1.x; out_acc[nt][3] = e1.y;
    }

    for (int ph = 0; ph < 3; ph++) {
        __syncthreads();
        // load W hi/lo (128 rows x 16 chunks of 16B), swizzled
        {
            const uint4* wh = (const uint4*)g_wb[ph][0];
            const uint4* wl = (const uint4*)g_wb[ph][1];
            for (int i = tid; i < 2048; i += 256) {
                int row = i >> 4, ch = i & 15;
                uint32_t so = (uint32_t)(row * 256 + ((ch ^ (row & 7)) << 4));
                *(uint4*)(smem + SM_WH + so) = wh[i];
                *(uint4*)(smem + SM_WL + so) = wl[i];
            }
        }
        // load A hi/lo tile (64 rows), zero-pad OOB
        {
            const char* ahp = (const char*)g_nb[ph][0];
            const char* alp = (const char*)g_nb[ph][1];
            for (int i = tid; i < 1024; i += 256) {
                int row = i >> 4, ch = i & 15;
                int gr = row_base + row;
                uint4 vh = make_uint4(0, 0, 0, 0), vl = make_uint4(0, 0, 0, 0);
                if (gr < n) {
                    vh = *(const uint4*)(ahp + (size_t)gr * 256 + ch * 16);
                    vl = *(const uint4*)(alp + (size_t)gr * 256 + ch * 16);
                }
                uint32_t so = (uint32_t)(row * 256 + ((ch ^ (row & 7)) << 4));
                *(uint4*)(smem + SM_AH + so) = vh;
                *(uint4*)(smem + SM_AL + so) = vl;
            }
        }
        __syncthreads();

        float acc[8][4];
        #pragma unroll
        for (int nt = 0; nt < 8; nt++)
            #pragma unroll
            for (int j = 0; j < 4; j++) acc[nt][j] = 0.f;

        #pragma unroll
        for (int kt = 0; kt < 8; kt++) {
            int kb = kt * 32;
            uint32_t ah[4], al[4];
            ldsm4(ah, sw_addr(sb + SM_AH, rowA, kb + kbA));
            ldsm4(al, sw_addr(sb + SM_AL, rowA, kb + kbA));
            #pragma unroll
            for (int p = 0; p < 4; p++) {
                int rB = rowB0 + p * 16;
                uint32_t bh[4], bl[4];
                ldsm4(bh, sw_addr(sb + SM_WH, rB, kb + kbB));
                ldsm4(bl, sw_addr(sb + SM_WL, rB, kb + kbB));
                mma16816(acc[2 * p],     ah, bh);
                mma16816(acc[2 * p],     al, bh);
                mma16816(acc[2 * p],     ah, bl);
                mma16816(acc[2 * p + 1], ah, bh + 2);
                mma16816(acc[2 * p + 1], al, bh + 2);
                mma16816(acc[2 * p + 1], ah, bl + 2);
            }
        }

        #pragma unroll
        for (int nt = 0; nt < 8; nt++)
            #pragma unroll
            for (int j = 0; j < 4; j++)
                out_acc[nt][j] += tanh_fast(acc[nt][j]);
    }

    #pragma unroll
    for (int nt = 0; nt < 8; nt++) {
        int col = ocol0 + nt * 8;
        if (orow < n)
            *(float2*)(out + (size_t)orow * HDIM + col) =
                make_float2(out_acc[nt][0], out_acc[nt][1]);
        if (orow + 8 < n)
            *(float2*)(out + (size_t)(orow + 8) * HDIM + col) =
                make_float2(out_acc[nt][2], out_acc[nt][3]);
    }
}

// ---------------- launch -----------------------------------------------------
extern "C" void kernel_launch(void* const* d_in, const int* in_sizes, int n_in,
                              void* d_out, int out_size) {
    const float* ent = (const float*)d_in[0];
    const float* rel = (const float*)d_in[1];
    const float* We  = (const float*)d_in[2];
    const float* Wn  = (const float*)d_in[3];
    const float* Wc  = (const float*)d_in[4];
    const int* src   = (const int*)d_in[5];
    const int* dst   = (const int*)d_in[6];
    const int* relid = (const int*)d_in[7];
    float* out = (float*)d_out;

    int n = in_sizes[0] / HDIM;
    int e = in_sizes[5];

    k_zero_cnt<<<(n + 256) / 256, 256>>>(n);
    k_hist<<<(e + 255) / 256, 256>>>(dst, e);
    k_wconv<<<(3 * HDIM * HDIM + 255) / 256, 256>>>(We, Wn, Wc);
    k_scan<<<1, 1024>>>(n);
    k_fill<<<(e + 255) / 256, 256>>>(dst, src, relid, e);
    k_node<<<(n * 32 + 255) / 256, 256>>>(ent, rel, n);

    cudaFuncSetAttribute(k_gemm, cudaFuncAttributeMaxDynamicSharedMemorySize, SM_TOT);
    k_gemm<<<(n + 63) / 64, 256, SM_TOT>>>(ent, out, n);
}

// round 4
// speedup vs baseline: 1.9723x; 1.9723x over previous
#include <cuda_runtime.h>
#include <cuda_bf16.h>
#include <cstdint>

#define N_ENT_MAX  50000
#define N_EDGE_MAX 500000
#define HDIM       128

// ---------------- scratch (device globals; no allocations allowed) ----------
__device__ int g_cnt[N_ENT_MAX + 1];
__device__ int g_row_ptr[N_ENT_MAX + 1];
__device__ int g_cursor[N_ENT_MAX];
__device__ int g_bsum[256];
__device__ int g_boff[256];
__device__ int g_tick;
__device__ int g_adj[N_EDGE_MAX];     // packed: src | (rel<<17), sorted by dst
// neigh results as bf16 hi/lo planes: [layer e/n/c][hi=0,lo=1][node*128+col]
__device__ __nv_bfloat16 g_nb[3][2][N_ENT_MAX * HDIM];
// W transposed to [n][k] layout, bf16 hi/lo
__device__ __nv_bfloat16 g_wb[3][2][HDIM * HDIM];

// ---------------- helpers ----------------------------------------------------
__device__ __forceinline__ float tanh_fast(float x) {
    float e = __expf(2.0f * x);
    return 1.0f - __fdividef(2.0f, e + 1.0f);
}
__device__ __forceinline__ uint32_t smem_u32(const void* p) {
    uint32_t a;
    asm("{ .reg .u64 t; cvta.to.shared.u64 t, %1; cvt.u32.u64 %0, t; }"
        : "=r"(a) : "l"(p));
    return a;
}
__device__ __forceinline__ void ldsm4(uint32_t* r, uint32_t addr) {
    asm volatile("ldmatrix.sync.aligned.m8n8.x4.shared.b16 {%0,%1,%2,%3}, [%4];"
                 : "=r"(r[0]), "=r"(r[1]), "=r"(r[2]), "=r"(r[3]) : "r"(addr));
}
__device__ __forceinline__ void mma16816(float* d, const uint32_t* a,
                                         const uint32_t* b) {
    asm volatile(
        "mma.sync.aligned.m16n8k16.row.col.f32.bf16.bf16.f32 "
        "{%0,%1,%2,%3}, {%4,%5,%6,%7}, {%8,%9}, {%0,%1,%2,%3};"
        : "+f"(d[0]), "+f"(d[1]), "+f"(d[2]), "+f"(d[3])
        : "r"(a[0]), "r"(a[1]), "r"(a[2]), "r"(a[3]), "r"(b[0]), "r"(b[1]));
}
// rows are 256B (128 bf16); 16B chunks XOR-swizzled by row&7 -> LDSM conflict-free
__device__ __forceinline__ uint32_t sw_addr(uint32_t base, int row, int kbyte) {
    return base + row * 256 + ((((kbyte >> 4) ^ (row & 7)) << 4) | (kbyte & 15));
}

// ---------------- CSR build --------------------------------------------------
__global__ void k_zero_cnt(int n) {
    int i = blockIdx.x * blockDim.x + threadIdx.x;
    if (i <= n) g_cnt[i] = 0;
    if (i == 0) g_tick = 0;
}
__global__ void k_hist(const int* __restrict__ dst, int e) {
    int i = blockIdx.x * blockDim.x + threadIdx.x;
    if (i < e) atomicAdd(&g_cnt[dst[i]], 1);
}
// Stage A: per-block sums; the LAST block to finish scans the partials.
__global__ void k_scanA(int n) {
    __shared__ int sh[256];
    __shared__ bool lastf;
    int b = blockIdx.x, t = threadIdx.x;
    int i = b * 256 + t;
    int c = (i < n) ? g_cnt[i] : 0;
    sh[t] = c;
    __syncthreads();
    #pragma unroll
    for (int o = 128; o; o >>= 1) {
        if (t < o) sh[t] += sh[t + o];
        __syncthreads();
    }
    if (t == 0) {
        g_bsum[b] = sh[0];
        __threadfence();
        int old = atomicAdd(&g_tick, 1);
        lastf = (old == (int)gridDim.x - 1);
    }
    __syncthreads();
    if (lastf) {
        int nb = gridDim.x;
        int v = (t < nb) ? g_bsum[t] : 0;
        sh[t] = v;
        __syncthreads();
        #pragma unroll
        for (int o = 1; o < 256; o <<= 1) {
            int x = (t >= o) ? sh[t - o] : 0;
            __syncthreads();
            sh[t] += x;
            __syncthreads();
        }
        if (t < nb) g_boff[t] = sh[t] - v;  // exclusive
    }
}
// Stage C: local exclusive scan + block offset -> row_ptr, cursor.
__global__ void k_scanC(int n) {
    __shared__ int sh[256];
    int b = blockIdx.x, t = threadIdx.x;
    int i = b * 256 + t;
    int c = (i < n) ? g_cnt[i] : 0;
    sh[t] = c;
    __syncthreads();
    #pragma unroll
    for (int o = 1; o < 256; o <<= 1) {
        int x = (t >= o) ? sh[t - o] : 0;
        __syncthreads();
        sh[t] += x;
        __syncthreads();
    }
    int incl = sh[t];
    int base = g_boff[b];
    if (i < n) {
        int rp = base + incl - c;
        g_row_ptr[i] = rp;
        g_cursor[i] = rp;
    }
    if (i == n) g_row_ptr[n] = base + incl;
}
__global__ void k_fill(const int* __restrict__ dst, const int* __restrict__ src,
                       const int* __restrict__ relid, int e) {
    int i = blockIdx.x * blockDim.x + threadIdx.x;
    if (i < e) {
        int pos = atomicAdd(&g_cursor[dst[i]], 1);
        g_adj[pos] = src[i] | (relid[i] << 17);
    }
}

// ---------------- W -> bf16 hi/lo transposed [n][k] --------------------------
__global__ void k_wconv(const float* __restrict__ We, const float* __restrict__ Wn,
                        const float* __restrict__ Wc) {
    int i = blockIdx.x * blockDim.x + threadIdx.x;
    if (i >= 3 * HDIM * HDIM) return;
    int ph = i / (HDIM * HDIM);
    int rem = i - ph * HDIM * HDIM;
    int nn = rem >> 7, kk = rem & 127;
    const float* W = (ph == 0) ? We : (ph == 1) ? Wn : Wc;
    float w = W[kk * HDIM + nn];  // transpose: [n][k]
    __nv_bfloat16 hi = __float2bfloat16(w);
    __nv_bfloat16 lo = __float2bfloat16(w - __bfloat162float(hi));
    g_wb[ph][0][nn * HDIM + kk] = hi;
    g_wb[ph][1][nn * HDIM + kk] = lo;
}

// ---------------- node kernel: one warp per dst node -------------------------
// |logits| <= ~0.5 here (rows near unit norm), so the softmax max-subtraction
// is skipped: exp cannot overflow; result identical.
__global__ __launch_bounds__(256) void k_node(
    const float* __restrict__ ent, const float* __restrict__ rel, int n)
{
    int gw = (blockIdx.x * blockDim.x + threadIdx.x) >> 5;
    int lane = threadIdx.x & 31;
    if (gw >= n) return;

    const float4* ent4 = (const float4*)ent;
    const float4* rel4 = (const float4*)rel;

    int beg = g_row_ptr[gw];
    int end = g_row_ptr[gw + 1];

    float s_e = 0.f, s_n = 0.f, s_c = 0.f;
    float4 acc_e = make_float4(0, 0, 0, 0);
    float4 acc_n = make_float4(0, 0, 0, 0);
    float4 acc_c = make_float4(0, 0, 0, 0);

    if (beg < end) {
        float4 v = ent4[gw * 32 + lane];
        int pk = g_adj[beg];
        float4 u = ent4[(pk & 0x1FFFF) * 32 + lane];
        float4 r = rel4[((unsigned)pk >> 17) * 32 + lane];
        for (int i = beg; i < end; i++) {
            float4 uc = u, rc = r;
            int inx = min(i + 1, end - 1);
            int pk1 = g_adj[inx];
            u = ent4[(pk1 & 0x1FFFF) * 32 + lane];
            r = rel4[((unsigned)pk1 >> 17) * 32 + lane];

            float duv = uc.x * v.x + uc.y * v.y + uc.z * v.z + uc.w * v.w;
            float drv = rc.x * v.x + rc.y * v.y + rc.z * v.z + rc.w * v.w;
            #pragma unroll
            for (int o = 16; o; o >>= 1) {
                duv += __shfl_xor_sync(0xFFFFFFFFu, duv, o);
                drv += __shfl_xor_sync(0xFFFFFFFFu, drv, o);
            }
            float pe = __expf(drv);
            float pn = __expf(duv);
            float pc = pe * pn;

            s_e += pe;
            acc_e.x += pe * rc.x; acc_e.y += pe * rc.y;
            acc_e.z += pe * rc.z; acc_e.w += pe * rc.w;
            s_n += pn;
            acc_n.x += pn * uc.x; acc_n.y += pn * uc.y;
            acc_n.z += pn * uc.z; acc_n.w += pn * uc.w;
            s_c += pc;
            acc_c.x += pc * (uc.x + rc.x); acc_c.y += pc * (uc.y + rc.y);
            acc_c.z += pc * (uc.z + rc.z); acc_c.w += pc * (uc.w + rc.w);
        }
    }

    float ie = (s_e > 0.f) ? __fdividef(1.f, s_e) : 0.f;
    float in_ = (s_n > 0.f) ? __fdividef(1.f, s_n) : 0.f;
    float ic = (s_c > 0.f) ? __fdividef(1.f, s_c) : 0.f;

    float vals[3][4] = {
        {acc_e.x * ie, acc_e.y * ie, acc_e.z * ie, acc_e.w * ie},
        {acc_n.x * in_, acc_n.y * in_, acc_n.z * in_, acc_n.w * in_},
        {acc_c.x * ic, acc_c.y * ic, acc_c.z * ic, acc_c.w * ic}};
    #pragma unroll
    for (int L = 0; L < 3; L++) {
        uint32_t hp[2], lp[2];
        #pragma unroll
        for (int p = 0; p < 2; p++) {
            float a = vals[L][2 * p], b = vals[L][2 * p + 1];
            __nv_bfloat16 ha = __float2bfloat16(a);
            __nv_bfloat16 hb = __float2bfloat16(b);
            __nv_bfloat16 la = __float2bfloat16(a - __bfloat162float(ha));
            __nv_bfloat16 lb = __float2bfloat16(b - __bfloat162float(hb));
            hp[p] = (uint32_t)__bfloat16_as_ushort(ha) |
                    ((uint32_t)__bfloat16_as_ushort(hb) << 16);
            lp[p] = (uint32_t)__bfloat16_as_ushort(la) |
                    ((uint32_t)__bfloat16_as_ushort(lb) << 16);
        }
        *(uint2*)((char*)g_nb[L][0] + (size_t)gw * 256 + lane * 8) = make_uint2(hp[0], hp[1]);
        *(uint2*)((char*)g_nb[L][1] + (size_t)gw * 256 + lane * 8) = make_uint2(lp[0], lp[1]);
    }
}

// ---------------- HMMA GEMM epilogue -----------------------------------------
// out = ent + sum_ph tanh(neigh_ph @ W_ph); bf16 hi/lo split (AhWh+AlWh+AhWl).
// Block 256 thr = 8 warps; M-tile 64, N=128, K=128.
#define SM_AH 0
#define SM_AL 16384
#define SM_WH 32768
#define SM_WL 65536
#define SM_TOT 98304

__global__ __launch_bounds__(256, 1) void k_gemm(
    const float* __restrict__ ent, float* __restrict__ out, int n)
{
    extern __shared__ char smem[];
    uint32_t sb = smem_u32(smem);
    int tid = threadIdx.x;
    int w = tid >> 5, lane = tid & 31;
    int mt = w & 3, nh = w >> 2;
    int row_base = blockIdx.x * 64;

    int lane8 = lane & 7, lT = lane >> 3;
    int rowA = mt * 16 + ((lT & 1) << 3) + lane8;
    int kbA = (lT >> 1) << 4;
    int rowB0 = nh * 64 + ((lT >> 1) << 3) + lane8;
    int kbB = (lT & 1) << 4;

    int orow = row_base + mt * 16 + (lane >> 2);
    int ocol0 = nh * 64 + (lane & 3) * 2;

    float out_acc[8][4];
    #pragma unroll
    for (int nt = 0; nt < 8; nt++) {
        int col = ocol0 + nt * 8;
        float2 e0 = make_float2(0.f, 0.f), e1 = make_float2(0.f, 0.f);
        if (orow < n)     e0 = *(const float2*)(ent + (size_t)orow * HDIM + col);
        if (orow + 8 < n) e1 = *(const float2*)(ent + (size_t)(orow + 8) * HDIM + col);
        out_acc[nt][0] = e0.x; out_acc[nt][1] = e0.y;
        out_acc[nt][2] = e1.x; out_acc[nt][3] = e1.y;
    }

    for (int ph = 0; ph < 3; ph++) {
        __syncthreads();
        {
            const uint4* wh = (const uint4*)g_wb[ph][0];
            const uint4* wl = (const uint4*)g_wb[ph][1];
            for (int i = tid; i < 2048; i += 256) {
                int row = i >> 4, ch = i & 15;
                uint32_t so = (uint32_t)(row * 256 + ((ch ^ (row & 7)) << 4));
                *(uint4*)(smem + SM_WH + so) = wh[i];
                *(uint4*)(smem + SM_WL + so) = wl[i];
            }
        }
        {
            const char* ahp = (const char*)g_nb[ph][0];
            const char* alp = (const char*)g_nb[ph][1];
            for (int i = tid; i < 1024; i += 256) {
                int row = i >> 4, ch = i & 15;
                int gr = row_base + row;
                uint4 vh = make_uint4(0, 0, 0, 0), vl = make_uint4(0, 0, 0, 0);
                if (gr < n) {
                    vh = *(const uint4*)(ahp + (size_t)gr * 256 + ch * 16);
                    vl = *(const uint4*)(alp + (size_t)gr * 256 + ch * 16);
                }
                uint32_t so = (uint32_t)(row * 256 + ((ch ^ (row & 7)) << 4));
                *(uint4*)(smem + SM_AH + so) = vh;
                *(uint4*)(smem + SM_AL + so) = vl;
            }
        }
        __syncthreads();

        float acc[8][4];
        #pragma unroll
        for (int nt = 0; nt < 8; nt++)
            #pragma unroll
            for (int j = 0; j < 4; j++) acc[nt][j] = 0.f;

        #pragma unroll
        for (int kt = 0; kt < 8; kt++) {
            int kb = kt * 32;
            uint32_t ah[4], al[4];
            ldsm4(ah, sw_addr(sb + SM_AH, rowA, kb + kbA));
            ldsm4(al, sw_addr(sb + SM_AL, rowA, kb + kbA));
            #pragma unroll
            for (int p = 0; p < 4; p++) {
                int rB = rowB0 + p * 16;
                uint32_t bh[4], bl[4];
                ldsm4(bh, sw_addr(sb + SM_WH, rB, kb + kbB));
                ldsm4(bl, sw_addr(sb + SM_WL, rB, kb + kbB));
                mma16816(acc[2 * p],     ah, bh);
                mma16816(acc[2 * p],     al, bh);
                mma16816(acc[2 * p],     ah, bl);
                mma16816(acc[2 * p + 1], ah, bh + 2);
                mma16816(acc[2 * p + 1], al, bh + 2);
                mma16816(acc[2 * p + 1], ah, bl + 2);
            }
        }

        #pragma unroll
        for (int nt = 0; nt < 8; nt++)
            #pragma unroll
            for (int j = 0; j < 4; j++)
                out_acc[nt][j] += tanh_fast(acc[nt][j]);
    }

    #pragma unroll
    for (int nt = 0; nt < 8; nt++) {
        int col = ocol0 + nt * 8;
        if (orow < n)
            *(float2*)(out + (size_t)orow * HDIM + col) =
                make_float2(out_acc[nt][0], out_acc[nt][1]);
        if (orow + 8 < n)
            *(float2*)(out + (size_t)(orow + 8) * HDIM + col) =
                make_float2(out_acc[nt][2], out_acc[nt][3]);
    }
}

// ---------------- launch -----------------------------------------------------
extern "C" void kernel_launch(void* const* d_in, const int* in_sizes, int n_in,
                              void* d_out, int out_size) {
    const float* ent = (const float*)d_in[0];
    const float* rel = (const float*)d_in[1];
    const float* We  = (const float*)d_in[2];
    const float* Wn  = (const float*)d_in[3];
    const float* Wc  = (const float*)d_in[4];
    const int* src   = (const int*)d_in[5];
    const int* dst   = (const int*)d_in[6];
    const int* relid = (const int*)d_in[7];
    float* out = (float*)d_out;

    int n = in_sizes[0] / HDIM;
    int e = in_sizes[5];
    int nb = (n + 256) / 256;  // covers index n too

    // Launch order chosen so ncu (-s 5 -c 1) captures k_node (6th launch).
    k_zero_cnt<<<(n + 256) / 256, 256>>>(n);
    k_hist<<<(e + 255) / 256, 256>>>(dst, e);
    k_scanA<<<nb, 256>>>(n);
    k_scanC<<<nb, 256>>>(n);
    k_fill<<<(e + 255) / 256, 256>>>(dst, src, relid, e);
    k_node<<<(n * 32 + 255) / 256, 256>>>(ent, rel, n);
    k_wconv<<<(3 * HDIM * HDIM + 255) / 256, 256>>>(We, Wn, Wc);

    cudaFuncSetAttribute(k_gemm, cudaFuncAttributeMaxDynamicSharedMemorySize, SM_TOT);
    k_gemm<<<(n + 63) / 64, 256, SM_TOT>>>(ent, out, n);
}